// round 9
// baseline (speedup 1.0000x reference)
#include <cuda_runtime.h>
#include <cuda_bf16.h>
#include <cstdint>

#define H 1024
#define E 64
#define TPC 128          // tokens per CTA (2 CTAs/SM)
#define KB 32            // K elements per chunk
#define NCHUNK (H / KB)  // 32

// Per-buffer SMEM: 3 x-planes [128 rows x 80B] + 3 w-planes [64 rows x 80B]
#define XPLANE 10240
#define WPLANE 5120
#define WS_OFF (3 * XPLANE)          // 30720 within a buffer
#define BUFSZ  (WS_OFF + 3 * WPLANE) // 46080
#define SMEM_TOTAL (2 * BUFSZ)       // 92160 -> 2 CTAs = 184320 <= 228KB
#define LSTRIDE 68                   // logits smem stride; 128*68*4 = 34816

__device__ __nv_bfloat16 g_w3[3 * E * H];   // pre-split W: [h|m|l][e][k]

// ---------------- helpers ----------------
__device__ __forceinline__ uint32_t smem_u32(const void* p) {
    uint32_t a;
    asm("{ .reg .u64 t; cvta.to.shared.u64 t, %1; cvt.u32.u64 %0, t; }"
        : "=r"(a) : "l"(p));
    return a;
}
__device__ __forceinline__ void ldsm4(uint32_t* r, uint32_t addr) {
    asm volatile("ldmatrix.sync.aligned.m8n8.x4.shared.b16 {%0,%1,%2,%3}, [%4];"
                 : "=r"(r[0]), "=r"(r[1]), "=r"(r[2]), "=r"(r[3]) : "r"(addr));
}
__device__ __forceinline__ void mma_bf16(float* d, const uint32_t* a, const uint32_t* b) {
    asm volatile(
        "mma.sync.aligned.m16n8k16.row.col.f32.bf16.bf16.f32 "
        "{%0,%1,%2,%3}, {%4,%5,%6,%7}, {%8,%9}, {%0,%1,%2,%3};"
        : "+f"(d[0]), "+f"(d[1]), "+f"(d[2]), "+f"(d[3])
        : "r"(a[0]), "r"(a[1]), "r"(a[2]), "r"(a[3]), "r"(b[0]), "r"(b[1]));
}
__device__ __forceinline__ void sts64(uint32_t addr, uint32_t a, uint32_t b) {
    asm volatile("st.shared.v2.b32 [%0], {%1, %2};" :: "r"(addr), "r"(a), "r"(b) : "memory");
}
__device__ __forceinline__ void sts128(uint32_t addr, uint4 v) {
    asm volatile("st.shared.v4.b32 [%0], {%1, %2, %3, %4};"
                 :: "r"(addr), "r"(v.x), "r"(v.y), "r"(v.z), "r"(v.w) : "memory");
}
// Pack (a,b) -> bf16x2 in one cvt; residuals recovered from the packed bits.
__device__ __forceinline__ uint32_t cvt2(float a, float b) {
    uint32_t r;
    asm("cvt.rn.bf16x2.f32 %0, %1, %2;" : "=r"(r) : "f"(b), "f"(a));
    return r;  // a in low 16, b in high 16
}
__device__ __forceinline__ uint32_t pack2(float a, float b, float& ra, float& rb) {
    uint32_t r = cvt2(a, b);
    ra = a - __uint_as_float(r << 16);
    rb = b - __uint_as_float(r & 0xFFFF0000u);
    return r;
}

// ---------------- W pre-split (h/m/l exact 3-way) ----------------
__global__ void convert_w_kernel(const float* __restrict__ W,
                                 float* __restrict__ out, int T) {
    int i = blockIdx.x * blockDim.x + threadIdx.x;
    if (i < E * H) {
        float v = W[i];
        __nv_bfloat16 h = __float2bfloat16(v);
        float r1 = v - __bfloat162float(h);
        __nv_bfloat16 m = __float2bfloat16(r1);
        float r2 = r1 - __bfloat162float(m);
        g_w3[i] = h;
        g_w3[E * H + i] = m;
        g_w3[2 * E * H + i] = __float2bfloat16(r2);   // exact: r2 has <= 8 sig bits
    }
    if (i == 0) out[4 * T] = 0.f;  // aux scalar output
}

// ---------------- main fused kernel (HMMA, double-buffered, 2 CTA/SM) ------
__global__ void __launch_bounds__(256, 2)
moe_gate_hmma(const float* __restrict__ x, float* __restrict__ out, int T) {
    extern __shared__ char smem[];
    const uint32_t sb = smem_u32(smem);
    float* const LS = (float*)smem;   // logits scratch (reused after mainloop)

    const int tid  = threadIdx.x;
    const int wid  = tid >> 5, lane = tid & 31;
    const int tg   = wid & 3;         // token group: rows tg*32..+31
    const int eg   = wid >> 2;        // expert group: cols eg*32..+31
    const int t0   = blockIdx.x * TPC;

    // ldmatrix lane address offsets
    const uint32_t a_lane = (uint32_t)((lane & 15) * 80 + (lane >> 4) * 16);
    const uint32_t b_lane = (uint32_t)(((lane >> 4) * 8 + (lane & 7)) * 80 +
                                       ((lane >> 3) & 1) * 16);
    const uint32_t a_base = (uint32_t)(tg * 32 * 80) + a_lane;
    const uint32_t b_base = (uint32_t)(eg * 32 * 80) + b_lane;

    // staging maps
    const int slot = tid & 7;   // x: float4 slot within 32-elem row
    const int rg   = tid >> 3;  // x: rows rg + 32*j  (j < 4)

    // Two accumulator banks: accB for h*h (magnitude ~1), accS for the 5
    // small products — keeps small-term rounding small (round-5 fix).
    float accB[2][4][4], accS[2][4][4];
    #pragma unroll
    for (int i = 0; i < 2; ++i)
        #pragma unroll
        for (int j = 0; j < 4; ++j)
            #pragma unroll
            for (int k = 0; k < 4; ++k) { accB[i][j][k] = 0.f; accS[i][j][k] = 0.f; }

    float4 xr[4];
    uint4  wr[3];

#define LOAD_X(cc)                                                               \
    do {                                                                         \
        const float* xb = x + (size_t)(t0 + rg) * H + (cc) * KB + slot * 4;      \
        _Pragma("unroll") for (int j = 0; j < 4; ++j)                            \
            xr[j] = *(const float4*)(xb + (size_t)j * 32 * H);                   \
    } while (0)

#define LOAD_W(cc)                                                               \
    do {                                                                         \
        _Pragma("unroll") for (int q = 0; q < 3; ++q) {                          \
            int gi = tid + 256 * q;                                              \
            int ws = gi & 3, wrow = gi >> 2;                                     \
            wr[q] = *(const uint4*)(g_w3 + ((wrow >> 6) * (E * H) +              \
                     (wrow & 63) * H + (cc) * KB + ws * 8));                     \
        }                                                                        \
    } while (0)

// Stage xr/wr into buffer at base bb (split x into 3 bf16 planes).
#define STAGE(bb)                                                                \
    do {                                                                         \
        const uint32_t XSb = (bb), WSb = (bb) + WS_OFF;                          \
        _Pragma("unroll") for (int j = 0; j < 4; ++j) {                          \
            int row = rg + 32 * j;                                               \
            uint32_t roff = (uint32_t)row * 80 + (uint32_t)slot * 8;             \
            float4 v = xr[j];                                                    \
            float r1x, r1y, r1z, r1w, r2x, r2y, r2z, r2w;                        \
            uint32_t h01 = pack2(v.x, v.y, r1x, r1y);                            \
            uint32_t h23 = pack2(v.z, v.w, r1z, r1w);                            \
            uint32_t m01 = pack2(r1x, r1y, r2x, r2y);                            \
            uint32_t m23 = pack2(r1z, r1w, r2z, r2w);                            \
            uint32_t l01 = cvt2(r2x, r2y);                                       \
            uint32_t l23 = cvt2(r2z, r2w);                                       \
            sts64(XSb + roff,              h01, h23);                            \
            sts64(XSb + XPLANE + roff,     m01, m23);                            \
            sts64(XSb + 2 * XPLANE + roff, l01, l23);                            \
        }                                                                        \
        _Pragma("unroll") for (int q = 0; q < 3; ++q) {                          \
            int gi = tid + 256 * q;                                              \
            int ws = gi & 3, wrow = gi >> 2;                                     \
            int pw = wrow >> 6, e = wrow & 63;                                   \
            sts128(WSb + (uint32_t)pw * WPLANE + (uint32_t)e * 80 +              \
                   (uint32_t)ws * 16, wr[q]);                                    \
        }                                                                        \
    } while (0)

    // prologue: stage chunk 0 into buffer 0
    LOAD_X(0);
    LOAD_W(0);
    STAGE(sb);
    __syncthreads();

    for (int c = 0; c < NCHUNK; ++c) {
        const uint32_t cbuf = sb + (uint32_t)(c & 1) * BUFSZ;
        const uint32_t nbuf = sb + (uint32_t)((c + 1) & 1) * BUFSZ;

        if (c + 1 < NCHUNK) {   // get next chunk's LDGs in flight first
            LOAD_X(c + 1);
            LOAD_W(c + 1);
        }

        // compute chunk c from cbuf: 2 k-steps x 6 products x (2x4) tiles
        const uint32_t XSc = cbuf, WSc = cbuf + WS_OFF;
        #pragma unroll
        for (int ks = 0; ks < 2; ++ks) {
            uint32_t bf[3][8];
            #pragma unroll
            for (int pw = 0; pw < 3; ++pw) {
                uint32_t wb = WSc + (uint32_t)pw * WPLANE + b_base + (uint32_t)ks * 32;
                ldsm4(&bf[pw][0], wb);
                ldsm4(&bf[pw][4], wb + 16 * 80);
            }
            #pragma unroll
            for (int px = 0; px < 3; ++px) {
                uint32_t af[2][4];
                #pragma unroll
                for (int i = 0; i < 2; ++i)
                    ldsm4(af[i], XSc + (uint32_t)px * XPLANE + a_base +
                                 (uint32_t)(i * 16 * 80) + (uint32_t)ks * 32);
                const int npw = (px == 0) ? 3 : (px == 1 ? 2 : 1);
                #pragma unroll
                for (int pw = 0; pw < 3; ++pw) {
                    if (pw < npw) {
                        const bool big = (px == 0) && (pw == 0);
                        #pragma unroll
                        for (int i = 0; i < 2; ++i)
                            #pragma unroll
                            for (int j = 0; j < 4; ++j)
                                mma_bf16(big ? accB[i][j] : accS[i][j], af[i],
                                         &bf[pw][(j >> 1) * 4 + (j & 1) * 2]);
                    }
                }
            }
        }

        // stage chunk c+1 into the other buffer (overlaps MMA drain)
        if (c + 1 < NCHUNK) STAGE(nbuf);

        __syncthreads();
    }

    // ---------------- epilogue: accums -> smem logits ----------------
    {
        int r0 = tg * 32 + (lane >> 2);
        int c0 = eg * 32 + 2 * (lane & 3);
        #pragma unroll
        for (int i = 0; i < 2; ++i)
            #pragma unroll
            for (int j = 0; j < 4; ++j) {
                int row = r0 + i * 16;
                int col = c0 + j * 8;
                LS[row * LSTRIDE + col]           = accB[i][j][0] + accS[i][j][0];
                LS[row * LSTRIDE + col + 1]       = accB[i][j][1] + accS[i][j][1];
                LS[(row + 8) * LSTRIDE + col]     = accB[i][j][2] + accS[i][j][2];
                LS[(row + 8) * LSTRIDE + col + 1] = accB[i][j][3] + accS[i][j][3];
            }
    }
    __syncthreads();

    // ---------------- softmax + top-2, one token per thread ----------------
    if (tid < TPC) {
        const int t = t0 + tid;
        float l[E];
        const float4* p = (const float4*)(LS + (size_t)tid * LSTRIDE);
        #pragma unroll
        for (int i = 0; i < E / 4; ++i) {
            float4 v = p[i];
            l[4*i] = v.x; l[4*i+1] = v.y; l[4*i+2] = v.z; l[4*i+3] = v.w;
        }

        float m = l[0];
        #pragma unroll
        for (int i = 1; i < E; ++i) m = fmaxf(m, l[i]);

        float s = 0.f;
        #pragma unroll
        for (int i = 0; i < E; ++i) s += expf(l[i] - m);

        int i1 = 0; float v1 = l[0];
        #pragma unroll
        for (int i = 1; i < E; ++i)
            if (l[i] > v1) { v1 = l[i]; i1 = i; }
        int i2 = -1; float v2 = -3.0e38f;
        #pragma unroll
        for (int i = 0; i < E; ++i)
            if (i != i1 && l[i] > v2) { v2 = l[i]; i2 = i; }

        float inv_s = 1.f / s;
        float p1 = expf(v1 - m) * inv_s;
        float p2 = expf(v2 - m) * inv_s;
        float e  = expf(p2 - p1);
        float f1 = 1.f / (1.f + e);
        float f2 = e / (1.f + e);

        out[2 * t]     = f1;
        out[2 * t + 1] = f2;
        out[2 * T + 2 * t]     = (float)i1;
        out[2 * T + 2 * t + 1] = (float)i2;
    }
}

extern "C" void kernel_launch(void* const* d_in, const int* in_sizes, int n_in,
                              void* d_out, int out_size) {
    const float* x = (const float*)d_in[0];   // [4, 8192, 1024] f32
    const float* W = (const float*)d_in[1];   // [64, 1024] f32
    float* out = (float*)d_out;
    const int T = in_sizes[0] / H;            // 32768

    cudaFuncSetAttribute(moe_gate_hmma,
                         cudaFuncAttributeMaxDynamicSharedMemorySize, SMEM_TOTAL);

    convert_w_kernel<<<(E * H + 255) / 256, 256>>>(W, out, T);
    moe_gate_hmma<<<T / TPC, 256, SMEM_TOTAL>>>(x, out, T);
}

// round 12
// speedup vs baseline: 1.1134x; 1.1134x over previous
#include <cuda_runtime.h>
#include <cuda_bf16.h>
#include <cstdint>

#define H 1024
#define E 64
#define TPC 256          // tokens per CTA
#define KB 32            // K elements per chunk
#define NCHUNK (H / KB)  // 32

// Per-buffer SMEM: 3 x-planes [256 rows x 80B] + 3 w-planes [64 rows x 80B]
#define XPLANE 20480
#define WPLANE 5120
#define WS_OFF (3 * XPLANE)          // 61440 within a buffer
#define BUFSZ  (WS_OFF + 3 * WPLANE) // 76800
#define SMEM_TOTAL (2 * BUFSZ)       // 153600 (1 CTA/SM)
#define LSTRIDE 68                   // logits smem stride; 256*68*4 = 69632

__device__ __nv_bfloat16 g_w3[3 * E * H];   // pre-split W: [h|m|l][e][k]

// ---------------- helpers ----------------
__device__ __forceinline__ uint32_t smem_u32(const void* p) {
    uint32_t a;
    asm("{ .reg .u64 t; cvta.to.shared.u64 t, %1; cvt.u32.u64 %0, t; }"
        : "=r"(a) : "l"(p));
    return a;
}
__device__ __forceinline__ void ldsm4(uint32_t* r, uint32_t addr) {
    asm volatile("ldmatrix.sync.aligned.m8n8.x4.shared.b16 {%0,%1,%2,%3}, [%4];"
                 : "=r"(r[0]), "=r"(r[1]), "=r"(r[2]), "=r"(r[3]) : "r"(addr));
}
__device__ __forceinline__ void mma_bf16(float* d, const uint32_t* a, const uint32_t* b) {
    asm volatile(
        "mma.sync.aligned.m16n8k16.row.col.f32.bf16.bf16.f32 "
        "{%0,%1,%2,%3}, {%4,%5,%6,%7}, {%8,%9}, {%0,%1,%2,%3};"
        : "+f"(d[0]), "+f"(d[1]), "+f"(d[2]), "+f"(d[3])
        : "r"(a[0]), "r"(a[1]), "r"(a[2]), "r"(a[3]), "r"(b[0]), "r"(b[1]));
}
__device__ __forceinline__ void sts64(uint32_t addr, uint32_t a, uint32_t b) {
    asm volatile("st.shared.v2.b32 [%0], {%1, %2};" :: "r"(addr), "r"(a), "r"(b) : "memory");
}
__device__ __forceinline__ void sts128(uint32_t addr, uint4 v) {
    asm volatile("st.shared.v4.b32 [%0], {%1, %2, %3, %4};"
                 :: "r"(addr), "r"(v.x), "r"(v.y), "r"(v.z), "r"(v.w) : "memory");
}
// Pack (a,b) -> bf16x2 in one cvt; residuals recovered from the packed bits.
__device__ __forceinline__ uint32_t cvt2(float a, float b) {
    uint32_t r;
    asm("cvt.rn.bf16x2.f32 %0, %1, %2;" : "=r"(r) : "f"(b), "f"(a));
    return r;  // a in low 16, b in high 16
}
__device__ __forceinline__ uint32_t pack2(float a, float b, float& ra, float& rb) {
    uint32_t r = cvt2(a, b);
    ra = a - __uint_as_float(r << 16);
    rb = b - __uint_as_float(r & 0xFFFF0000u);
    return r;
}

// ---------------- W pre-split (h/m/l exact 3-way) ----------------
__global__ void convert_w_kernel(const float* __restrict__ W,
                                 float* __restrict__ out, int T) {
    int i = blockIdx.x * blockDim.x + threadIdx.x;
    if (i < E * H) {
        float v = W[i];
        __nv_bfloat16 h = __float2bfloat16(v);
        float r1 = v - __bfloat162float(h);
        __nv_bfloat16 m = __float2bfloat16(r1);
        float r2 = r1 - __bfloat162float(m);
        g_w3[i] = h;
        g_w3[E * H + i] = m;
        g_w3[2 * E * H + i] = __float2bfloat16(r2);   // exact: r2 has <= 8 sig bits
    }
    if (i == 0) out[4 * T] = 0.f;  // aux scalar output
}

// ---------------- main fused kernel ----------------------------------------
// Per chunk: 12 groups of 32 MMAs; one staging "piece" interleaved after each
// group so STS/ALU issue in tensor-queue stall gaps (not after the drain).
// Pipeline depth 2: pieces stage chunk c+1 (regs loaded during chunk c-1),
// then immediately reload that register with chunk c+2's LDG.
__global__ void __launch_bounds__(256, 1)
moe_gate_hmma(const float* __restrict__ x, float* __restrict__ out, int T) {
    extern __shared__ char smem[];
    const uint32_t sb = smem_u32(smem);
    float* const LS = (float*)smem;   // logits scratch (reused after mainloop)

    const int tid  = threadIdx.x;
    const int wid  = tid >> 5, lane = tid & 31;
    const int tg   = wid & 3;         // token group: rows tg*64..+63
    const int eg   = wid >> 2;        // expert group: cols eg*32..+31
    const int t0   = blockIdx.x * TPC;

    // ldmatrix lane address offsets
    const uint32_t a_lane = (uint32_t)((lane & 15) * 80 + (lane >> 4) * 16);
    const uint32_t b_lane = (uint32_t)(((lane >> 4) * 8 + (lane & 7)) * 80 +
                                       ((lane >> 3) & 1) * 16);
    const uint32_t a_base = (uint32_t)(tg * 64 * 80) + a_lane;
    const uint32_t b_base = (uint32_t)(eg * 32 * 80) + b_lane;

    // staging maps
    const int slot = tid & 7;   // x: float4 slot within 32-elem row
    const int rg   = tid >> 3;  // x: rows rg + 32*j

    // Two accumulator banks (round-5 numeric fix, validated).
    float accB[4][4][4], accS[4][4][4];
    #pragma unroll
    for (int i = 0; i < 4; ++i)
        #pragma unroll
        for (int j = 0; j < 4; ++j)
            #pragma unroll
            for (int k = 0; k < 4; ++k) { accB[i][j][k] = 0.f; accS[i][j][k] = 0.f; }

    float4 xr[8];
    uint4  wr[3];
    const float* xbase = x + (size_t)(t0 + rg) * H + slot * 4;

#define LOAD_X(cc)                                                               \
    do {                                                                         \
        _Pragma("unroll") for (int j = 0; j < 8; ++j)                            \
            xr[j] = *(const float4*)(xbase + (cc) * KB + (size_t)j * 32 * H);    \
    } while (0)

#define LOAD_W(cc)                                                               \
    do {                                                                         \
        _Pragma("unroll") for (int q = 0; q < 3; ++q) {                          \
            int gi = tid + 256 * q;                                              \
            int ws = gi & 3, wrow = gi >> 2;                                     \
            wr[q] = *(const uint4*)(g_w3 + ((wrow >> 6) * (E * H) +              \
                     (wrow & 63) * H + (cc) * KB + ws * 8));                     \
        }                                                                        \
    } while (0)

// Full stage (prologue only).
#define STAGE(bb)                                                                \
    do {                                                                         \
        const uint32_t XSb = (bb), WSb = (bb) + WS_OFF;                          \
        _Pragma("unroll") for (int j = 0; j < 8; ++j) {                          \
            int row = rg + 32 * j;                                               \
            uint32_t roff = (uint32_t)row * 80 + (uint32_t)slot * 8;             \
            float4 v = xr[j];                                                    \
            float r1x, r1y, r1z, r1w, r2x, r2y, r2z, r2w;                        \
            uint32_t h01 = pack2(v.x, v.y, r1x, r1y);                            \
            uint32_t h23 = pack2(v.z, v.w, r1z, r1w);                            \
            uint32_t m01 = pack2(r1x, r1y, r2x, r2y);                            \
            uint32_t m23 = pack2(r1z, r1w, r2z, r2w);                            \
            uint32_t l01 = cvt2(r2x, r2y);                                       \
            uint32_t l23 = cvt2(r2z, r2w);                                       \
            sts64(XSb + roff,              h01, h23);                            \
            sts64(XSb + XPLANE + roff,     m01, m23);                            \
            sts64(XSb + 2 * XPLANE + roff, l01, l23);                            \
        }                                                                        \
        _Pragma("unroll") for (int q = 0; q < 3; ++q) {                          \
            int gi = tid + 256 * q;                                              \
            int ws = gi & 3, wrow = gi >> 2;                                     \
            int pw = wrow >> 6, e = wrow & 63;                                   \
            sts128(WSb + (uint32_t)pw * WPLANE + (uint32_t)e * 80 +              \
                   (uint32_t)ws * 16, wr[q]);                                    \
        }                                                                        \
    } while (0)

// Piece: stage x row j of chunk c+1 into nbuf, then reload xr[j] with c+2.
#define PIECE_X(j)                                                               \
    do {                                                                         \
        if (c + 1 < NCHUNK) {                                                    \
            int row = rg + 32 * (j);                                             \
            uint32_t roff = (uint32_t)row * 80 + (uint32_t)slot * 8;             \
            float4 v = xr[j];                                                    \
            float r1x, r1y, r1z, r1w, r2x, r2y, r2z, r2w;                        \
            uint32_t h01 = pack2(v.x, v.y, r1x, r1y);                            \
            uint32_t h23 = pack2(v.z, v.w, r1z, r1w);                            \
            uint32_t m01 = pack2(r1x, r1y, r2x, r2y);                            \
            uint32_t m23 = pack2(r1z, r1w, r2z, r2w);                            \
            uint32_t l01 = cvt2(r2x, r2y);                                       \
            uint32_t l23 = cvt2(r2z, r2w);                                       \
            sts64(XSn + roff,              h01, h23);                            \
            sts64(XSn + XPLANE + roff,     m01, m23);                            \
            sts64(XSn + 2 * XPLANE + roff, l01, l23);                            \
        }                                                                        \
        if (c + 2 < NCHUNK)                                                      \
            xr[j] = *(const float4*)(xbase + (c + 2) * KB + (size_t)(j) * 32 * H); \
    } while (0)

// Piece: stage W part q of chunk c+1, then reload wr[q] with c+2.
#define PIECE_W(q)                                                               \
    do {                                                                         \
        int gi = tid + 256 * (q);                                                \
        int ws = gi & 3, wrow = gi >> 2;                                         \
        int pw = wrow >> 6, e = wrow & 63;                                       \
        if (c + 1 < NCHUNK)                                                      \
            sts128(WSn + (uint32_t)pw * WPLANE + (uint32_t)e * 80 +              \
                   (uint32_t)ws * 16, wr[q]);                                    \
        if (c + 2 < NCHUNK)                                                      \
            wr[q] = *(const uint4*)(g_w3 + (pw * (E * H) + e * H +               \
                     (c + 2) * KB + ws * 8));                                    \
    } while (0)

#define LDB(ksv)                                                                 \
    do {                                                                         \
        _Pragma("unroll") for (int pw = 0; pw < 3; ++pw) {                       \
            uint32_t wb = WSc + (uint32_t)pw * WPLANE + b_base + (ksv) * 32;     \
            ldsm4(&bf[pw][0], wb);                                               \
            ldsm4(&bf[pw][4], wb + 16 * 80);                                     \
        }                                                                        \
    } while (0)

#define LDA(ksv, pxv)                                                            \
    do {                                                                         \
        _Pragma("unroll") for (int i = 0; i < 4; ++i)                            \
            ldsm4(af[i], XSc + (pxv) * XPLANE + a_base +                         \
                         (uint32_t)(i * 16 * 80) + (ksv) * 32);                  \
    } while (0)

#define GRP(pwv, BANK)                                                           \
    do {                                                                         \
        _Pragma("unroll") for (int i = 0; i < 4; ++i)                            \
            _Pragma("unroll") for (int j = 0; j < 4; ++j)                        \
                mma_bf16(BANK[i][j], af[i], &bf[pwv][(j >> 1) * 4 + (j & 1) * 2]); \
    } while (0)

    // prologue: stage chunk 0 into buffer 0; prefetch chunk 1 into regs
    LOAD_X(0);
    LOAD_W(0);
    STAGE(sb);
    LOAD_X(1);
    LOAD_W(1);
    __syncthreads();

    for (int c = 0; c < NCHUNK; ++c) {
        const uint32_t cbuf = sb + (uint32_t)(c & 1) * BUFSZ;
        const uint32_t nbuf = sb + (uint32_t)((c + 1) & 1) * BUFSZ;
        const uint32_t XSc = cbuf, WSc = cbuf + WS_OFF;
        const uint32_t XSn = nbuf, WSn = nbuf + WS_OFF;

        uint32_t bf[3][8];
        uint32_t af[4][4];

        // ks = 0
        LDB(0);
        LDA(0, 0);
        GRP(0, accB);  PIECE_X(0);
        GRP(1, accS);  PIECE_X(1);
        GRP(2, accS);  PIECE_X(2);
        LDA(0, 1);
        GRP(0, accS);  PIECE_X(3);
        GRP(1, accS);  PIECE_X(4);
        LDA(0, 2);
        GRP(0, accS);  PIECE_X(5);

        // ks = 1
        LDB(1);
        LDA(1, 0);
        GRP(0, accB);  PIECE_X(6);
        GRP(1, accS);  PIECE_X(7);
        GRP(2, accS);  PIECE_W(0);
        LDA(1, 1);
        GRP(0, accS);  PIECE_W(1);
        GRP(1, accS);  PIECE_W(2);
        LDA(1, 2);
        GRP(0, accS);

        __syncthreads();
    }

    // ---------------- epilogue: accums -> smem logits ----------------
    {
        int r0 = tg * 64 + (lane >> 2);
        int c0 = eg * 32 + 2 * (lane & 3);
        #pragma unroll
        for (int i = 0; i < 4; ++i)
            #pragma unroll
            for (int j = 0; j < 4; ++j) {
                int row = r0 + i * 16;
                int col = c0 + j * 8;
                LS[row * LSTRIDE + col]           = accB[i][j][0] + accS[i][j][0];
                LS[row * LSTRIDE + col + 1]       = accB[i][j][1] + accS[i][j][1];
                LS[(row + 8) * LSTRIDE + col]     = accB[i][j][2] + accS[i][j][2];
                LS[(row + 8) * LSTRIDE + col + 1] = accB[i][j][3] + accS[i][j][3];
            }
    }
    __syncthreads();

    // ---------------- softmax + top-2, one token per thread ----------------
    {
        const int t = t0 + tid;
        float l[E];
        const float4* p = (const float4*)(LS + (size_t)tid * LSTRIDE);
        #pragma unroll
        for (int i = 0; i < E / 4; ++i) {
            float4 v = p[i];
            l[4*i] = v.x; l[4*i+1] = v.y; l[4*i+2] = v.z; l[4*i+3] = v.w;
        }

        float m = l[0];
        #pragma unroll
        for (int i = 1; i < E; ++i) m = fmaxf(m, l[i]);

        float s = 0.f;
        #pragma unroll
        for (int i = 0; i < E; ++i) s += expf(l[i] - m);

        int i1 = 0; float v1 = l[0];
        #pragma unroll
        for (int i = 1; i < E; ++i)
            if (l[i] > v1) { v1 = l[i]; i1 = i; }
        int i2 = -1; float v2 = -3.0e38f;
        #pragma unroll
        for (int i = 0; i < E; ++i)
            if (i != i1 && l[i] > v2) { v2 = l[i]; i2 = i; }

        float inv_s = 1.f / s;
        float p1 = expf(v1 - m) * inv_s;
        float p2 = expf(v2 - m) * inv_s;
        float e  = expf(p2 - p1);
        float f1 = 1.f / (1.f + e);
        float f2 = e / (1.f + e);

        out[2 * t]     = f1;
        out[2 * t + 1] = f2;
        out[2 * T + 2 * t]     = (float)i1;
        out[2 * T + 2 * t + 1] = (float)i2;
    }
}

extern "C" void kernel_launch(void* const* d_in, const int* in_sizes, int n_in,
                              void* d_out, int out_size) {
    const float* x = (const float*)d_in[0];   // [4, 8192, 1024] f32
    const float* W = (const float*)d_in[1];   // [64, 1024] f32
    float* out = (float*)d_out;
    const int T = in_sizes[0] / H;            // 32768

    cudaFuncSetAttribute(moe_gate_hmma,
                         cudaFuncAttributeMaxDynamicSharedMemorySize, SMEM_TOTAL);

    convert_w_kernel<<<(E * H + 255) / 256, 256>>>(W, out, T);
    moe_gate_hmma<<<T / TPC, 256, SMEM_TOTAL>>>(x, out, T);
}

// round 15
// speedup vs baseline: 1.3183x; 1.1840x over previous
#include <cuda_runtime.h>
#include <cuda_bf16.h>
#include <cstdint>

#define H 1024
#define E 64
#define TPC 256          // tokens per CTA
#define KB 32            // K elements per chunk
#define NCHUNK (H / KB)  // 32

// Per-buffer SMEM: 3 x-planes [256 rows x 80B] + 3 w-planes [64 rows x 80B]
#define XPLANE 20480
#define WPLANE 5120
#define WS_OFF (3 * XPLANE)          // 61440 within a buffer
#define BUFSZ  (WS_OFF + 3 * WPLANE) // 76800
#define SMEM_TOTAL (2 * BUFSZ)       // 153600 (1 CTA/SM)
#define LSTRIDE 68                   // logits smem stride; 256*68*4 = 69632

__device__ __nv_bfloat16 g_w3[3 * E * H];   // pre-split W: [h|m|l][e][k]

// ---------------- helpers ----------------
__device__ __forceinline__ uint32_t smem_u32(const void* p) {
    uint32_t a;
    asm("{ .reg .u64 t; cvta.to.shared.u64 t, %1; cvt.u32.u64 %0, t; }"
        : "=r"(a) : "l"(p));
    return a;
}
__device__ __forceinline__ void ldsm4(uint32_t* r, uint32_t addr) {
    asm volatile("ldmatrix.sync.aligned.m8n8.x4.shared.b16 {%0,%1,%2,%3}, [%4];"
                 : "=r"(r[0]), "=r"(r[1]), "=r"(r[2]), "=r"(r[3]) : "r"(addr));
}
__device__ __forceinline__ void mma_bf16(float* d, const uint32_t* a, const uint32_t* b) {
    asm volatile(
        "mma.sync.aligned.m16n8k16.row.col.f32.bf16.bf16.f32 "
        "{%0,%1,%2,%3}, {%4,%5,%6,%7}, {%8,%9}, {%0,%1,%2,%3};"
        : "+f"(d[0]), "+f"(d[1]), "+f"(d[2]), "+f"(d[3])
        : "r"(a[0]), "r"(a[1]), "r"(a[2]), "r"(a[3]), "r"(b[0]), "r"(b[1]));
}
__device__ __forceinline__ void sts64(uint32_t addr, uint32_t a, uint32_t b) {
    asm volatile("st.shared.v2.b32 [%0], {%1, %2};" :: "r"(addr), "r"(a), "r"(b) : "memory");
}
__device__ __forceinline__ void sts128(uint32_t addr, uint4 v) {
    asm volatile("st.shared.v4.b32 [%0], {%1, %2, %3, %4};"
                 :: "r"(addr), "r"(v.x), "r"(v.y), "r"(v.z), "r"(v.w) : "memory");
}
// Pack (a,b) -> bf16x2 in one cvt; residuals recovered from the packed bits.
__device__ __forceinline__ uint32_t cvt2(float a, float b) {
    uint32_t r;
    asm("cvt.rn.bf16x2.f32 %0, %1, %2;" : "=r"(r) : "f"(b), "f"(a));
    return r;  // a in low 16, b in high 16
}
__device__ __forceinline__ uint32_t pack2(float a, float b, float& ra, float& rb) {
    uint32_t r = cvt2(a, b);
    ra = a - __uint_as_float(r << 16);
    rb = b - __uint_as_float(r & 0xFFFF0000u);
    return r;
}

// ---------------- W pre-split (h/m/l exact 3-way) ----------------
__global__ void convert_w_kernel(const float* __restrict__ W,
                                 float* __restrict__ out, int T) {
    int i = blockIdx.x * blockDim.x + threadIdx.x;
    if (i < E * H) {
        float v = W[i];
        __nv_bfloat16 h = __float2bfloat16(v);
        float r1 = v - __bfloat162float(h);
        __nv_bfloat16 m = __float2bfloat16(r1);
        float r2 = r1 - __bfloat162float(m);
        g_w3[i] = h;
        g_w3[E * H + i] = m;
        g_w3[2 * E * H + i] = __float2bfloat16(r2);   // exact: r2 has <= 8 sig bits
    }
    if (i == 0) out[4 * T] = 0.f;  // aux scalar output
}

// ---------------- main fused kernel (HMMA, phase-skewed warps) -------------
// Phase-0 warps (eg==0): STAGE(c+1) -> LOAD(c+2) -> MMA(c)
// Phase-1 warps (eg==1): MMA(c) -> STAGE(c+1) -> LOAD(c+2)
// Each SMSP hosts one warp of each phase, so one warp feeds the tensor pipe
// while the other issues staging ALU/STS — removes the per-chunk drain bubble.
__global__ void __launch_bounds__(256, 1)
moe_gate_hmma(const float* __restrict__ x, float* __restrict__ out, int T) {
    extern __shared__ char smem[];
    const uint32_t sb = smem_u32(smem);
    float* const LS = (float*)smem;   // logits scratch (reused after mainloop)

    const int tid  = threadIdx.x;
    const int wid  = tid >> 5, lane = tid & 31;
    const int tg   = wid & 3;         // token group: rows tg*64..+63
    const int eg   = wid >> 2;        // expert group: cols eg*32..+31 (also phase)
    const int t0   = blockIdx.x * TPC;

    // ldmatrix lane address offsets
    const uint32_t a_lane = (uint32_t)((lane & 15) * 80 + (lane >> 4) * 16);
    const uint32_t b_lane = (uint32_t)(((lane >> 4) * 8 + (lane & 7)) * 80 +
                                       ((lane >> 3) & 1) * 16);
    const uint32_t a_base = (uint32_t)(tg * 64 * 80) + a_lane;
    const uint32_t b_base = (uint32_t)(eg * 32 * 80) + b_lane;

    // staging maps
    const int slot = tid & 7;   // x: float4 slot within 32-elem row
    const int rg   = tid >> 3;  // x: rows rg + 32*j

    // Two accumulator banks (round-5 numeric fix, validated).
    float accB[4][4][4], accS[4][4][4];
    #pragma unroll
    for (int i = 0; i < 4; ++i)
        #pragma unroll
        for (int j = 0; j < 4; ++j)
            #pragma unroll
            for (int k = 0; k < 4; ++k) { accB[i][j][k] = 0.f; accS[i][j][k] = 0.f; }

    float4 xr[8];
    uint4  wr[3];

#define LOAD_X(cc)                                                               \
    do {                                                                         \
        const float* xb = x + (size_t)(t0 + rg) * H + (cc) * KB + slot * 4;      \
        _Pragma("unroll") for (int j = 0; j < 8; ++j)                            \
            xr[j] = *(const float4*)(xb + (size_t)j * 32 * H);                   \
    } while (0)

#define LOAD_W(cc)                                                               \
    do {                                                                         \
        _Pragma("unroll") for (int q = 0; q < 3; ++q) {                          \
            int gi = tid + 256 * q;                                              \
            int ws = gi & 3, wrow = gi >> 2;                                     \
            wr[q] = *(const uint4*)(g_w3 + ((wrow >> 6) * (E * H) +              \
                     (wrow & 63) * H + (cc) * KB + ws * 8));                     \
        }                                                                        \
    } while (0)

// Stage xr/wr into buffer at base bb (split x into 3 bf16 planes).
#define STAGE(bb)                                                                \
    do {                                                                         \
        const uint32_t XSb = (bb), WSb = (bb) + WS_OFF;                          \
        _Pragma("unroll") for (int j = 0; j < 8; ++j) {                          \
            int row = rg + 32 * j;                                               \
            uint32_t roff = (uint32_t)row * 80 + (uint32_t)slot * 8;             \
            float4 v = xr[j];                                                    \
            float r1x, r1y, r1z, r1w, r2x, r2y, r2z, r2w;                        \
            uint32_t h01 = pack2(v.x, v.y, r1x, r1y);                            \
            uint32_t h23 = pack2(v.z, v.w, r1z, r1w);                            \
            uint32_t m01 = pack2(r1x, r1y, r2x, r2y);                            \
            uint32_t m23 = pack2(r1z, r1w, r2z, r2w);                            \
            uint32_t l01 = cvt2(r2x, r2y);                                       \
            uint32_t l23 = cvt2(r2z, r2w);                                       \
            sts64(XSb + roff,              h01, h23);                            \
            sts64(XSb + XPLANE + roff,     m01, m23);                            \
            sts64(XSb + 2 * XPLANE + roff, l01, l23);                            \
        }                                                                        \
        _Pragma("unroll") for (int q = 0; q < 3; ++q) {                          \
            int gi = tid + 256 * q;                                              \
            int ws = gi & 3, wrow = gi >> 2;                                     \
            int pw = wrow >> 6, e = wrow & 63;                                   \
            sts128(WSb + (uint32_t)pw * WPLANE + (uint32_t)e * 80 +              \
                   (uint32_t)ws * 16, wr[q]);                                    \
        }                                                                        \
    } while (0)

// The 192-MMA compute block for chunk c from cbuf.
#define COMPUTE()                                                                \
    do {                                                                         \
        const uint32_t XSc = cbuf, WSc = cbuf + WS_OFF;                          \
        _Pragma("unroll") for (int ks = 0; ks < 2; ++ks) {                       \
            uint32_t bf[3][8];                                                   \
            _Pragma("unroll") for (int pw = 0; pw < 3; ++pw) {                   \
                uint32_t wb = WSc + (uint32_t)pw * WPLANE + b_base +             \
                              (uint32_t)ks * 32;                                 \
                ldsm4(&bf[pw][0], wb);                                           \
                ldsm4(&bf[pw][4], wb + 16 * 80);                                 \
            }                                                                    \
            _Pragma("unroll") for (int px = 0; px < 3; ++px) {                   \
                uint32_t af[4][4];                                               \
                _Pragma("unroll") for (int i = 0; i < 4; ++i)                    \
                    ldsm4(af[i], XSc + (uint32_t)px * XPLANE + a_base +          \
                                 (uint32_t)(i * 16 * 80) + (uint32_t)ks * 32);   \
                const int npw = (px == 0) ? 3 : (px == 1 ? 2 : 1);               \
                _Pragma("unroll") for (int pw = 0; pw < 3; ++pw) {               \
                    if (pw < npw) {                                              \
                        const bool big = (px == 0) && (pw == 0);                 \
                        _Pragma("unroll") for (int i = 0; i < 4; ++i)            \
                            _Pragma("unroll") for (int j = 0; j < 4; ++j)        \
                                mma_bf16(big ? accB[i][j] : accS[i][j], af[i],   \
                                         &bf[pw][(j >> 1) * 4 + (j & 1) * 2]);   \
                    }                                                            \
                }                                                                \
            }                                                                    \
        }                                                                        \
    } while (0)

    // prologue: stage chunk 0 into buffer 0; prefetch chunk 1 into regs
    LOAD_X(0);
    LOAD_W(0);
    STAGE(sb);
    LOAD_X(1);
    LOAD_W(1);
    __syncthreads();

    // invariant at iteration c start: cbuf holds chunk c, regs hold chunk c+1
    for (int c = 0; c < NCHUNK; ++c) {
        const uint32_t cbuf = sb + (uint32_t)(c & 1) * BUFSZ;
        const uint32_t nbuf = sb + (uint32_t)((c + 1) & 1) * BUFSZ;

        if (eg == 0) {   // phase 0: stage + reload, then MMA
            if (c + 1 < NCHUNK) STAGE(nbuf);
            if (c + 2 < NCHUNK) { LOAD_X(c + 2); LOAD_W(c + 2); }
            COMPUTE();
        } else {         // phase 1: MMA, then stage + reload
            COMPUTE();
            if (c + 1 < NCHUNK) STAGE(nbuf);
            if (c + 2 < NCHUNK) { LOAD_X(c + 2); LOAD_W(c + 2); }
        }

        __syncthreads();
    }

    // ---------------- epilogue: accums -> smem logits ----------------
    {
        int r0 = tg * 64 + (lane >> 2);
        int c0 = eg * 32 + 2 * (lane & 3);
        #pragma unroll
        for (int i = 0; i < 4; ++i)
            #pragma unroll
            for (int j = 0; j < 4; ++j) {
                int row = r0 + i * 16;
                int col = c0 + j * 8;
                LS[row * LSTRIDE + col]           = accB[i][j][0] + accS[i][j][0];
                LS[row * LSTRIDE + col + 1]       = accB[i][j][1] + accS[i][j][1];
                LS[(row + 8) * LSTRIDE + col]     = accB[i][j][2] + accS[i][j][2];
                LS[(row + 8) * LSTRIDE + col + 1] = accB[i][j][3] + accS[i][j][3];
            }
    }
    __syncthreads();

    // ---------------- softmax + top-2, one token per thread ----------------
    {
        const int t = t0 + tid;
        float l[E];
        const float4* p = (const float4*)(LS + (size_t)tid * LSTRIDE);
        #pragma unroll
        for (int i = 0; i < E / 4; ++i) {
            float4 v = p[i];
            l[4*i] = v.x; l[4*i+1] = v.y; l[4*i+2] = v.z; l[4*i+3] = v.w;
        }

        float m = l[0];
        #pragma unroll
        for (int i = 1; i < E; ++i) m = fmaxf(m, l[i]);

        float s = 0.f;
        #pragma unroll
        for (int i = 0; i < E; ++i) s += expf(l[i] - m);

        int i1 = 0; float v1 = l[0];
        #pragma unroll
        for (int i = 1; i < E; ++i)
            if (l[i] > v1) { v1 = l[i]; i1 = i; }
        int i2 = -1; float v2 = -3.0e38f;
        #pragma unroll
        for (int i = 0; i < E; ++i)
            if (i != i1 && l[i] > v2) { v2 = l[i]; i2 = i; }

        float inv_s = 1.f / s;
        float p1 = expf(v1 - m) * inv_s;
        float p2 = expf(v2 - m) * inv_s;
        float e  = expf(p2 - p1);
        float f1 = 1.f / (1.f + e);
        float f2 = e / (1.f + e);

        out[2 * t]     = f1;
        out[2 * t + 1] = f2;
        out[2 * T + 2 * t]     = (float)i1;
        out[2 * T + 2 * t + 1] = (float)i2;
    }
}

extern "C" void kernel_launch(void* const* d_in, const int* in_sizes, int n_in,
                              void* d_out, int out_size) {
    const float* x = (const float*)d_in[0];   // [4, 8192, 1024] f32
    const float* W = (const float*)d_in[1];   // [64, 1024] f32
    float* out = (float*)d_out;
    const int T = in_sizes[0] / H;            // 32768

    cudaFuncSetAttribute(moe_gate_hmma,
                         cudaFuncAttributeMaxDynamicSharedMemorySize, SMEM_TOTAL);

    convert_w_kernel<<<(E * H + 255) / 256, 256>>>(W, out, T);
    moe_gate_hmma<<<T / TPC, 256, SMEM_TOTAL>>>(x, out, T);
}